// round 3
// baseline (speedup 1.0000x reference)
#include <cuda_runtime.h>
#include <math.h>

#define N 4096
#define TILE 64                // output tile edge
#define HALO 2                 // 2 fused Jacobi steps
#define LDIM (TILE + 2 * HALO) // 68: loaded region per block
#define MDIM (TILE + 2)        // 66: intermediate region per block
#define BTHREADS 1024

// Static ping-pong scratch (allocation-free rule: __device__ globals only).
__device__ float g_buf0[N * N];
__device__ float g_buf1[N * N];

__global__ void init_gauss_kernel(const float* __restrict__ X,
                                  const float* __restrict__ Y,
                                  float* __restrict__ u) {
    int i = blockIdx.x * blockDim.x + threadIdx.x;
    if (i < N * N) {
        float dx = X[i] - 0.5f;
        float dy = Y[i] - 0.5f;
        u[i] = expf(-50.0f * (dx * dx + dy * dy));
    }
}

// Two fused Jacobi steps with zero Dirichlet boundary.
// Block: 1024 threads producing a 64x64 output tile (4 outputs/thread).
__global__ __launch_bounds__(BTHREADS, 2)
void jacobi2_kernel(const float* __restrict__ u, float* __restrict__ v) {
    __shared__ float s_u[LDIM][LDIM + 1];
    __shared__ float s_m[MDIM][MDIM + 1];

    const int ox = blockIdx.x * TILE;  // output tile origin
    const int oy = blockIdx.y * TILE;
    const int tid = threadIdx.y * blockDim.x + threadIdx.x;

    // Phase 1: cooperative load of 68x68 region with halo 2 (coalesced rows).
    #pragma unroll
    for (int i = tid; i < LDIM * LDIM; i += BTHREADS) {
        int ly = i / LDIM;
        int lx = i - ly * LDIM;
        int gy = oy - HALO + ly;
        int gx = ox - HALO + lx;
        float val = 0.0f;
        if (gx >= 0 && gx < N && gy >= 0 && gy < N)
            val = __ldg(&u[gy * N + gx]);
        s_u[ly][lx] = val;
    }
    __syncthreads();

    // Phase 2: first Jacobi step over 66x66 intermediate region.
    // s_m[a][b] = step-1 value at global (oy-1+a, ox-1+b).
    #pragma unroll
    for (int i = tid; i < MDIM * MDIM; i += BTHREADS) {
        int ly = i / MDIM;
        int lx = i - ly * MDIM;
        int gy = oy - 1 + ly;
        int gx = ox - 1 + lx;
        float val = 0.0f;
        if (gx >= 1 && gx < N - 1 && gy >= 1 && gy < N - 1) {
            val = 0.25f * (s_u[ly][lx + 1] + s_u[ly + 2][lx + 1] +
                           s_u[ly + 1][lx] + s_u[ly + 1][lx + 2]);
        }
        s_m[ly][lx] = val;
    }
    __syncthreads();

    // Phase 3: second Jacobi step, 4 outputs per thread (coalesced rows).
    #pragma unroll
    for (int i = tid; i < TILE * TILE; i += BTHREADS) {
        int yy = i / TILE;
        int xx = i - yy * TILE;
        int gy = oy + yy;
        int gx = ox + xx;
        float val = 0.0f;
        if (gx >= 1 && gx < N - 1 && gy >= 1 && gy < N - 1) {
            val = 0.25f * (s_m[yy][xx + 1] + s_m[yy + 2][xx + 1] +
                           s_m[yy + 1][xx] + s_m[yy + 1][xx + 2]);
        }
        v[gy * N + gx] = val;
    }
}

extern "C" void kernel_launch(void* const* d_in, const int* in_sizes, int n_in,
                              void* d_out, int out_size) {
    const float* X = (const float*)d_in[0];
    const float* Y = (const float*)d_in[1];
    float* out = (float*)d_out;

    float* buf0 = nullptr;
    float* buf1 = nullptr;
    cudaGetSymbolAddress((void**)&buf0, g_buf0);
    cudaGetSymbolAddress((void**)&buf1, g_buf1);

    // Initial condition into buf0.
    {
        int total = N * N;
        int threads = 256;
        int blocks = (total + threads - 1) / threads;
        init_gauss_kernel<<<blocks, threads>>>(X, Y, buf0);
    }

    // 100 Jacobi steps = 50 fused double-steps; last writes d_out.
    dim3 block(32, 32);
    dim3 grid(N / TILE, N / TILE);
    const int NPAIR = 50;
    for (int t = 0; t < NPAIR; ++t) {
        const float* src = (t % 2 == 0) ? buf0 : buf1;
        float* dst = (t == NPAIR - 1) ? out : ((t % 2 == 0) ? buf1 : buf0);
        jacobi2_kernel<<<grid, block>>>(src, dst);
    }
}

// round 6
// speedup vs baseline: 1.2853x; 1.2853x over previous
#include <cuda_runtime.h>
#include <math.h>

#define N 4096
#define TILE 64                 // output tile edge
#define LROWS 68                // loaded rows (halo 2 each side)
#define SROW 72                 // loaded cols: [ox-4, ox+68) for float4 alignment
#define MD 66                   // intermediate region edge
#define MROW 68                 // s_m row stride (float4-aligned stores)
#define BTHREADS 1024

// Static ping-pong scratch (allocation-free rule: __device__ globals only).
__device__ float g_buf0[N * N];
__device__ float g_buf1[N * N];

__global__ void init_gauss_kernel(const float* __restrict__ X,
                                  const float* __restrict__ Y,
                                  float* __restrict__ u) {
    int i = blockIdx.x * blockDim.x + threadIdx.x;
    if (i < N * N) {
        float dx = X[i] - 0.5f;
        float dy = Y[i] - 0.5f;
        u[i] = expf(-50.0f * (dx * dx + dy * dy));
    }
}

// Two fused Jacobi steps, zero Dirichlet boundary.
// 1024 threads produce a 64x64 output tile.
// s_u[r][c] = u[oy-2+r][ox-4+c]   (r<68, c<72)
// s_m[a][b] = step-1 value at (oy-1+a, ox-1+b)   (a<66, b<66; stride 68)
__global__ __launch_bounds__(BTHREADS, 2)
void jacobi2_kernel(const float* __restrict__ u, float* __restrict__ v) {
    __shared__ float s_u[LROWS * SROW];
    __shared__ float s_m[MD * MROW];

    const int tid = threadIdx.x;
    const int ox = blockIdx.x * TILE;
    const int oy = blockIdx.y * TILE;
    const bool interior = (blockIdx.x > 0) & (blockIdx.x < gridDim.x - 1) &
                          (blockIdx.y > 0) & (blockIdx.y < gridDim.y - 1);

    if (interior) {
        // ---- Phase 1: 68 rows x 18 float4 vector loads (coalesced). ----
        #pragma unroll
        for (int k = 0; k < 2; ++k) {
            int i = tid + k * BTHREADS;
            if (i < LROWS * 18) {
                int r = i / 18;
                int c4 = (i - r * 18) << 2;
                float4 val = *(const float4*)(u + (oy - 2 + r) * N + (ox - 4) + c4);
                *(float4*)(s_u + r * SROW + c4) = val;
            }
        }
        __syncthreads();

        // ---- Phase 2: step 1 over 66 rows x 68 cols (17 float4/row). ----
        // Cols 66,67 are harmless over-compute (s_u provides up to col 71).
        #pragma unroll
        for (int k = 0; k < 2; ++k) {
            int i = tid + k * BTHREADS;
            if (i < MD * 17) {
                int a = i / 17;
                int b4 = (i - a * 17) << 2;
                const float* p = s_u + a * SROW + b4;   // row a, col b4
                float4 o;
                o.x = 0.25f * (p[3] + p[2 * SROW + 3] + p[SROW + 2] + p[SROW + 4]);
                o.y = 0.25f * (p[4] + p[2 * SROW + 4] + p[SROW + 3] + p[SROW + 5]);
                o.z = 0.25f * (p[5] + p[2 * SROW + 5] + p[SROW + 4] + p[SROW + 6]);
                o.w = 0.25f * (p[6] + p[2 * SROW + 6] + p[SROW + 5] + p[SROW + 7]);
                *(float4*)(s_m + a * MROW + b4) = o;
            }
        }
        __syncthreads();

        // ---- Phase 3: step 2, one float4 output per thread (loop-free). ----
        {
            int yy = tid >> 4;             // 0..63
            int xx0 = (tid & 15) << 2;     // 0..60
            const float* top = s_m + yy * MROW + xx0;
            const float* mid = top + MROW;
            const float* bot = mid + MROW;
            float4 o;
            o.x = 0.25f * (top[1] + bot[1] + mid[0] + mid[2]);
            o.y = 0.25f * (top[2] + bot[2] + mid[1] + mid[3]);
            o.z = 0.25f * (top[3] + bot[3] + mid[2] + mid[4]);
            o.w = 0.25f * (top[4] + bot[4] + mid[3] + mid[5]);
            *(float4*)(v + (oy + yy) * N + ox + xx0) = o;
        }
    } else {
        // ---- Boundary blocks: guarded scalar path (252 of 4096 blocks). ----
        for (int i = tid; i < LROWS * SROW; i += BTHREADS) {
            int r = i / SROW;
            int c = i - r * SROW;
            int gy = oy - 2 + r, gx = ox - 4 + c;
            float val = 0.0f;
            if (gx >= 0 && gx < N && gy >= 0 && gy < N) val = u[gy * N + gx];
            s_u[i] = val;
        }
        __syncthreads();
        for (int i = tid; i < MD * MD; i += BTHREADS) {
            int a = i / MD;
            int b = i - a * MD;
            int gy = oy - 1 + a, gx = ox - 1 + b;
            float val = 0.0f;
            if (gx >= 1 && gx < N - 1 && gy >= 1 && gy < N - 1) {
                const float* p = s_u + a * SROW + b;
                val = 0.25f * (p[3] + p[2 * SROW + 3] + p[SROW + 2] + p[SROW + 4]);
            }
            s_m[a * MROW + b] = val;
        }
        __syncthreads();
        for (int i = tid; i < TILE * TILE; i += BTHREADS) {
            int yy = i >> 6;
            int xx = i & 63;
            int gy = oy + yy, gx = ox + xx;
            float val = 0.0f;
            if (gx >= 1 && gx < N - 1 && gy >= 1 && gy < N - 1) {
                const float* p = s_m + yy * MROW + xx;
                val = 0.25f * (p[1] + p[2 * MROW + 1] + p[MROW] + p[MROW + 2]);
            }
            v[gy * N + gx] = val;
        }
    }
}

extern "C" void kernel_launch(void* const* d_in, const int* in_sizes, int n_in,
                              void* d_out, int out_size) {
    const float* X = (const float*)d_in[0];
    const float* Y = (const float*)d_in[1];
    float* out = (float*)d_out;

    float* buf0 = nullptr;
    float* buf1 = nullptr;
    cudaGetSymbolAddress((void**)&buf0, g_buf0);
    cudaGetSymbolAddress((void**)&buf1, g_buf1);

    // Initial condition into buf0.
    {
        int total = N * N;
        int threads = 256;
        int blocks = (total + threads - 1) / threads;
        init_gauss_kernel<<<blocks, threads>>>(X, Y, buf0);
    }

    // 100 Jacobi steps = 50 fused double-steps; last writes d_out.
    dim3 block(BTHREADS);
    dim3 grid(N / TILE, N / TILE);
    const int NPAIR = 50;
    for (int t = 0; t < NPAIR; ++t) {
        const float* src = (t % 2 == 0) ? buf0 : buf1;
        float* dst = (t == NPAIR - 1) ? out : ((t % 2 == 0) ? buf1 : buf0);
        jacobi2_kernel<<<grid, block>>>(src, dst);
    }
}

// round 10
// speedup vs baseline: 1.5212x; 1.1835x over previous
#include <cuda_runtime.h>
#include <math.h>

#define N 4096
#define TILE 64                 // output tile edge
#define LROWS 68                // loaded rows (halo 2 each side)
#define SROW 72                 // loaded cols: [ox-4, ox+68) for float4 alignment
#define MD 66                   // intermediate region edge (boundary path)
#define MROW 68                 // s_m row stride (boundary path)
#define BTHREADS 1024

// Static ping-pong scratch (allocation-free rule: __device__ globals only).
__device__ float g_buf0[N * N];
__device__ float g_buf1[N * N];

__global__ void init_gauss_kernel(const float* __restrict__ X,
                                  const float* __restrict__ Y,
                                  float* __restrict__ u) {
    int i = blockIdx.x * blockDim.x + threadIdx.x;
    if (i < N * N) {
        float dx = X[i] - 0.5f;
        float dy = Y[i] - 0.5f;
        u[i] = expf(-50.0f * (dx * dx + dy * dy));
    }
}

// Two fused Jacobi steps, zero Dirichlet boundary.
// Interior blocks: single 13-point stencil (exact expansion of 2 steps).
// s_u[r][c] = u[oy-2+r][ox-4+c]   (r<68, c<72)
__global__ __launch_bounds__(BTHREADS, 2)
void jacobi2_kernel(const float* __restrict__ u, float* __restrict__ v) {
    __shared__ float s_u[LROWS * SROW];
    __shared__ float s_m[MD * MROW];   // used only by boundary blocks

    const int tid = threadIdx.x;
    const int ox = blockIdx.x * TILE;
    const int oy = blockIdx.y * TILE;
    const bool interior = (blockIdx.x > 0) & (blockIdx.x < gridDim.x - 1) &
                          (blockIdx.y > 0) & (blockIdx.y < gridDim.y - 1);

    if (interior) {
        // ---- Phase 1: 68 rows x 18 float4 vector loads (coalesced). ----
        #pragma unroll
        for (int k = 0; k < 2; ++k) {
            int i = tid + k * BTHREADS;
            if (i < LROWS * 18) {
                int r = i / 18;
                int c4 = (i - r * 18) << 2;
                float4 val = *(const float4*)(u + (oy - 2 + r) * N + (ox - 4) + c4);
                *(float4*)(s_u + r * SROW + c4) = val;
            }
        }
        __syncthreads();

        // ---- 13-point double-step: one float4 output per thread. ----
        // out[y][x] = (1/16)(4 u[y][x] + 2(u[y±1][x±1]) + u[y±2][x] + u[y][x±2])
        {
            const int yy = tid >> 4;                 // output row 0..63
            const int xx0 = (tid & 15) << 2;         // output col 0..60
            const float* base = s_u + yy * SROW + (xx0 + 4);

            float4 t  = *(const float4*)(base);                 // u[y-2][x..x+3]
            float4 al = *(const float4*)(base + SROW - 4);      // u[y-1][x-4..x-1]
            float4 am = *(const float4*)(base + SROW);          // u[y-1][x..x+3]
            float4 ar = *(const float4*)(base + SROW + 4);      // u[y-1][x+4..x+7]
            float4 bl = *(const float4*)(base + 2 * SROW - 4);  // u[y]  [x-4..x-1]
            float4 bm = *(const float4*)(base + 2 * SROW);      // u[y]  [x..x+3]
            float4 br = *(const float4*)(base + 2 * SROW + 4);  // u[y]  [x+4..x+7]
            float4 cl = *(const float4*)(base + 3 * SROW - 4);  // u[y+1][x-4..x-1]
            float4 cm = *(const float4*)(base + 3 * SROW);      // u[y+1][x..x+3]
            float4 cr = *(const float4*)(base + 3 * SROW + 4);  // u[y+1][x+4..x+7]
            float4 d  = *(const float4*)(base + 4 * SROW);      // u[y+2][x..x+3]

            const float k16 = 0.0625f;
            float4 o;
            // i = 0
            {
                float diag = (al.w + am.y) + (cl.w + cm.y);
                float far  = (t.x + d.x) + (bl.z + bm.z);
                o.x = (fmaf(4.0f, bm.x, far) + 2.0f * diag) * k16;
            }
            // i = 1
            {
                float diag = (am.x + am.z) + (cm.x + cm.z);
                float far  = (t.y + d.y) + (bl.w + bm.w);
                o.y = (fmaf(4.0f, bm.y, far) + 2.0f * diag) * k16;
            }
            // i = 2
            {
                float diag = (am.y + am.w) + (cm.y + cm.w);
                float far  = (t.z + d.z) + (bm.x + br.x);
                o.z = (fmaf(4.0f, bm.z, far) + 2.0f * diag) * k16;
            }
            // i = 3
            {
                float diag = (am.z + ar.x) + (cm.z + cr.x);
                float far  = (t.w + d.w) + (bm.y + br.y);
                o.w = (fmaf(4.0f, bm.w, far) + 2.0f * diag) * k16;
            }
            *(float4*)(v + (oy + yy) * N + ox + xx0) = o;
        }
    } else {
        // ---- Boundary blocks: guarded two-phase path (252 of 4096). ----
        for (int i = tid; i < LROWS * SROW; i += BTHREADS) {
            int r = i / SROW;
            int c = i - r * SROW;
            int gy = oy - 2 + r, gx = ox - 4 + c;
            float val = 0.0f;
            if (gx >= 0 && gx < N && gy >= 0 && gy < N) val = u[gy * N + gx];
            s_u[i] = val;
        }
        __syncthreads();
        for (int i = tid; i < MD * MD; i += BTHREADS) {
            int a = i / MD;
            int b = i - a * MD;
            int gy = oy - 1 + a, gx = ox - 1 + b;
            float val = 0.0f;
            if (gx >= 1 && gx < N - 1 && gy >= 1 && gy < N - 1) {
                const float* p = s_u + a * SROW + b;
                val = 0.25f * (p[3] + p[2 * SROW + 3] + p[SROW + 2] + p[SROW + 4]);
            }
            s_m[a * MROW + b] = val;
        }
        __syncthreads();
        for (int i = tid; i < TILE * TILE; i += BTHREADS) {
            int yy = i >> 6;
            int xx = i & 63;
            int gy = oy + yy, gx = ox + xx;
            float val = 0.0f;
            if (gx >= 1 && gx < N - 1 && gy >= 1 && gy < N - 1) {
                const float* p = s_m + yy * MROW + xx;
                val = 0.25f * (p[1] + p[2 * MROW + 1] + p[MROW] + p[MROW + 2]);
            }
            v[gy * N + gx] = val;
        }
    }
}

extern "C" void kernel_launch(void* const* d_in, const int* in_sizes, int n_in,
                              void* d_out, int out_size) {
    const float* X = (const float*)d_in[0];
    const float* Y = (const float*)d_in[1];
    float* out = (float*)d_out;

    float* buf0 = nullptr;
    float* buf1 = nullptr;
    cudaGetSymbolAddress((void**)&buf0, g_buf0);
    cudaGetSymbolAddress((void**)&buf1, g_buf1);

    // Initial condition into buf0.
    {
        int total = N * N;
        int threads = 256;
        int blocks = (total + threads - 1) / threads;
        init_gauss_kernel<<<blocks, threads>>>(X, Y, buf0);
    }

    // 100 Jacobi steps = 50 fused double-steps; last writes d_out.
    dim3 block(BTHREADS);
    dim3 grid(N / TILE, N / TILE);
    const int NPAIR = 50;
    for (int t = 0; t < NPAIR; ++t) {
        const float* src = (t % 2 == 0) ? buf0 : buf1;
        float* dst = (t == NPAIR - 1) ? out : ((t % 2 == 0) ? buf1 : buf0);
        jacobi2_kernel<<<grid, block>>>(src, dst);
    }
}

// round 14
// speedup vs baseline: 2.1316x; 1.4012x over previous
#include <cuda_runtime.h>
#include <math.h>

#define N 4096
#define TILE 64
#define BTHREADS 1024

// Static ping-pong scratch (allocation-free rule: __device__ globals only).
__device__ float g_buf0[N * N];
__device__ float g_buf1[N * N];

__global__ void init_gauss_kernel(const float* __restrict__ X,
                                  const float* __restrict__ Y,
                                  float* __restrict__ u) {
    int i = blockIdx.x * blockDim.x + threadIdx.x;
    if (i < N * N) {
        float dx = X[i] - 0.5f;
        float dy = Y[i] - 0.5f;
        u[i] = expf(-50.0f * (dx * dx + dy * dy));
    }
}

// Step-1 intermediate with zero Dirichlet clamp, computed on the fly.
__device__ __forceinline__ float jstep(const float* __restrict__ u, int y, int x) {
    if (y < 1 || y > N - 2 || x < 1 || x > N - 2) return 0.0f;
    return 0.25f * (u[(y - 1) * N + x] + u[(y + 1) * N + x] +
                    u[y * N + x - 1] + u[y * N + x + 1]);
}

// Two fused Jacobi steps, zero Dirichlet boundary. NO shared memory, NO barriers.
// Interior blocks: exact 13-point expansion, 11 coalesced LDG.128 per thread.
// out[y][x] = (1/16)(4 u[y][x] + 2 u[y±1][x±1] + u[y±2][x] + u[y][x±2])
__global__ __launch_bounds__(BTHREADS)
void jacobi2_kernel(const float* __restrict__ u, float* __restrict__ v) {
    const int tid = threadIdx.x;
    const int ox = blockIdx.x * TILE;
    const int oy = blockIdx.y * TILE;
    const bool interior = (blockIdx.x > 0) & (blockIdx.x < gridDim.x - 1) &
                          (blockIdx.y > 0) & (blockIdx.y < gridDim.y - 1);

    if (interior) {
        const int yy = tid >> 4;             // output row 0..63
        const int xx0 = (tid & 15) << 2;     // output col 0..60
        const int gy = oy + yy;
        const int gx = ox + xx0;
        const float* base = u + (gy - 2) * N + gx;   // row y-2, col x (16B aligned)

        float4 t  = *(const float4*)(base);              // u[y-2][x..x+3]
        float4 al = *(const float4*)(base + N - 4);      // u[y-1][x-4..x-1]
        float4 am = *(const float4*)(base + N);          // u[y-1][x..x+3]
        float4 ar = *(const float4*)(base + N + 4);      // u[y-1][x+4..x+7]
        float4 bl = *(const float4*)(base + 2 * N - 4);  // u[y]  [x-4..x-1]
        float4 bm = *(const float4*)(base + 2 * N);      // u[y]  [x..x+3]
        float4 br = *(const float4*)(base + 2 * N + 4);  // u[y]  [x+4..x+7]
        float4 cl = *(const float4*)(base + 3 * N - 4);  // u[y+1][x-4..x-1]
        float4 cm = *(const float4*)(base + 3 * N);      // u[y+1][x..x+3]
        float4 cr = *(const float4*)(base + 3 * N + 4);  // u[y+1][x+4..x+7]
        float4 d  = *(const float4*)(base + 4 * N);      // u[y+2][x..x+3]

        const float k16 = 0.0625f;
        float4 o;
        {
            float diag = (al.w + am.y) + (cl.w + cm.y);
            float far  = (t.x + d.x) + (bl.z + bm.z);
            o.x = (fmaf(4.0f, bm.x, far) + 2.0f * diag) * k16;
        }
        {
            float diag = (am.x + am.z) + (cm.x + cm.z);
            float far  = (t.y + d.y) + (bl.w + bm.w);
            o.y = (fmaf(4.0f, bm.y, far) + 2.0f * diag) * k16;
        }
        {
            float diag = (am.y + am.w) + (cm.y + cm.w);
            float far  = (t.z + d.z) + (bm.x + br.x);
            o.z = (fmaf(4.0f, bm.z, far) + 2.0f * diag) * k16;
        }
        {
            float diag = (am.z + ar.x) + (cm.z + cr.x);
            float far  = (t.w + d.w) + (bm.y + br.y);
            o.w = (fmaf(4.0f, bm.w, far) + 2.0f * diag) * k16;
        }
        *(float4*)(v + gy * N + gx) = o;
    } else {
        // Boundary blocks (252/4096): on-the-fly guarded path, 4 outputs/thread.
        #pragma unroll
        for (int k = 0; k < 4; ++k) {
            int i = tid + k * BTHREADS;
            int yy = i >> 6;
            int xx = i & 63;
            int gy = oy + yy, gx = ox + xx;
            float val = 0.0f;
            if (gx >= 1 && gx < N - 1 && gy >= 1 && gy < N - 1) {
                val = 0.25f * (jstep(u, gy - 1, gx) + jstep(u, gy + 1, gx) +
                               jstep(u, gy, gx - 1) + jstep(u, gy, gx + 1));
            }
            v[gy * N + gx] = val;
        }
    }
}

extern "C" void kernel_launch(void* const* d_in, const int* in_sizes, int n_in,
                              void* d_out, int out_size) {
    const float* X = (const float*)d_in[0];
    const float* Y = (const float*)d_in[1];
    float* out = (float*)d_out;

    float* buf0 = nullptr;
    float* buf1 = nullptr;
    cudaGetSymbolAddress((void**)&buf0, g_buf0);
    cudaGetSymbolAddress((void**)&buf1, g_buf1);

    // Initial condition into buf0.
    {
        int total = N * N;
        int threads = 256;
        int blocks = (total + threads - 1) / threads;
        init_gauss_kernel<<<blocks, threads>>>(X, Y, buf0);
    }

    // 100 Jacobi steps = 50 fused double-steps; last writes d_out.
    dim3 block(BTHREADS);
    dim3 grid(N / TILE, N / TILE);
    const int NPAIR = 50;
    for (int t = 0; t < NPAIR; ++t) {
        const float* src = (t % 2 == 0) ? buf0 : buf1;
        float* dst = (t == NPAIR - 1) ? out : ((t % 2 == 0) ? buf1 : buf0);
        jacobi2_kernel<<<grid, block>>>(src, dst);
    }
}